// round 2
// baseline (speedup 1.0000x reference)
#include <cuda_runtime.h>
#include <math.h>

#define NN 50000
#define EE 800000
#define IN_DIM 128
#define HD 128
#define HD2 64
#define OUT_DIM 1000
#define KHOPS 10
#define EPSV 1e-5f

// ---------------- scratch (device globals; no allocation allowed) ------------
__device__ float g_Y[(size_t)NN * HD];     // pre-BN scratch (reused all layers)
__device__ float g_H1[(size_t)NN * HD];    // layer-1 output (residual identity)
__device__ float g_CUR[(size_t)NN * HD];   // hop ping
__device__ float g_NXT[(size_t)NN * HD];   // hop pong
__device__ float g_OUT[(size_t)NN * HD];   // softmax-weighted accumulator
__device__ float g_H3[(size_t)NN * HD2];
__device__ float g_S1[HD], g_Q1[HD], g_S2[HD], g_Q2[HD], g_S3[HD2], g_Q3[HD2];
__device__ float g_w[KHOPS + 1];
__device__ int   g_deg[NN];
__device__ int   g_rowptr[NN + 1];
__device__ int   g_cursor[NN];
__device__ int   g_colidx[EE];

// ---------------- init: zero stats/degrees, softmax(att) ---------------------
__global__ void k_init(const float* __restrict__ att) {
    int t = blockIdx.x * blockDim.x + threadIdx.x;
    int stride = gridDim.x * blockDim.x;
    for (int i = t; i < NN; i += stride) g_deg[i] = 0;
    if (t < HD)  { g_S1[t] = 0.f; g_Q1[t] = 0.f; g_S2[t] = 0.f; g_Q2[t] = 0.f; }
    if (t < HD2) { g_S3[t] = 0.f; g_Q3[t] = 0.f; }
    if (t == 0) {
        float m = -1e30f;
        for (int i = 0; i <= KHOPS; i++) m = fmaxf(m, att[i]);
        float e[KHOPS + 1]; float s = 0.f;
        for (int i = 0; i <= KHOPS; i++) { e[i] = expf(att[i] - m); s += e[i]; }
        for (int i = 0; i <= KHOPS; i++) g_w[i] = e[i] / s;
    }
}

// ---------------- guarded tiled GEMM: C[M,Nc] = A[M,K] @ B[K,Nc] + bias ------
// BM=BN=64, BK=16, 256 threads, 4x4 register tile per thread.
__global__ __launch_bounds__(256)
void k_gemm(const float* __restrict__ A, const float* __restrict__ B,
            const float* __restrict__ bias, float* __restrict__ C,
            int M, int Nc, int K) {
    __shared__ float As[64][17];
    __shared__ float Bs[16][68];
    int tid = threadIdx.x;
    int tx = tid & 15, ty = tid >> 4;
    int rowBase = blockIdx.y * 64;
    int colBase = blockIdx.x * 64;
    float acc[4][4] = {};

    for (int k0 = 0; k0 < K; k0 += 16) {
        {   // load A tile: 64 rows x 16 k, one float4 per thread
            int r = tid >> 2, c = (tid & 3) * 4;
            int gr = rowBase + r;
            float4 v = make_float4(0.f, 0.f, 0.f, 0.f);
            if (gr < M) v = *(const float4*)(A + (size_t)gr * K + k0 + c);
            As[r][c] = v.x; As[r][c + 1] = v.y; As[r][c + 2] = v.z; As[r][c + 3] = v.w;
        }
        {   // load B tile: 16 k x 64 cols, one float4 per thread
            int r = tid >> 4, c = (tid & 15) * 4;
            int gc = colBase + c;
            float4 v = make_float4(0.f, 0.f, 0.f, 0.f);
            if (gc < Nc) v = *(const float4*)(B + (size_t)(k0 + r) * Nc + gc);
            Bs[r][c] = v.x; Bs[r][c + 1] = v.y; Bs[r][c + 2] = v.z; Bs[r][c + 3] = v.w;
        }
        __syncthreads();
        #pragma unroll
        for (int kk = 0; kk < 16; kk++) {
            float a[4], b[4];
            #pragma unroll
            for (int i = 0; i < 4; i++) a[i] = As[ty * 4 + i][kk];
            #pragma unroll
            for (int j = 0; j < 4; j++) b[j] = Bs[kk][tx * 4 + j];
            #pragma unroll
            for (int i = 0; i < 4; i++)
                #pragma unroll
                for (int j = 0; j < 4; j++)
                    acc[i][j] = fmaf(a[i], b[j], acc[i][j]);
        }
        __syncthreads();
    }
    #pragma unroll
    for (int i = 0; i < 4; i++) {
        int r = rowBase + ty * 4 + i;
        if (r >= M) continue;
        #pragma unroll
        for (int j = 0; j < 4; j++) {
            int c = colBase + tx * 4 + j;
            if (c < Nc) C[(size_t)r * Nc + c] = acc[i][j] + bias[c];
        }
    }
}

// ---------------- column sum / sumsq for BatchNorm (training stats) ----------
__global__ void k_stats(const float* __restrict__ Y, float* __restrict__ S,
                        float* __restrict__ Q, int M, int C) {
    int j = threadIdx.x;  // C threads
    float s = 0.f, q = 0.f;
    for (int r = blockIdx.x; r < M; r += gridDim.x) {
        float v = Y[(size_t)r * C + j];
        s += v; q += v * v;
    }
    atomicAdd(S + j, s);
    atomicAdd(Q + j, q);
}

// ---------------- BN apply + ReLU (+residual) (+seed OUT = w0*h) -------------
__global__ void k_apply(const float* __restrict__ Y, const float* __restrict__ g,
                        const float* __restrict__ be, const float* __restrict__ S,
                        const float* __restrict__ Q, float* __restrict__ H,
                        const float* __restrict__ resid, float* __restrict__ outw,
                        int M, int C) {
    int j = threadIdx.x;
    float mean = S[j] / (float)M;
    float var = Q[j] / (float)M - mean * mean;
    float rstd = rsqrtf(var + EPSV);
    float scale = g[j] * rstd;
    float shift = be[j] - mean * scale;
    float w0 = outw ? g_w[0] : 0.f;
    for (int r = blockIdx.x; r < M; r += gridDim.x) {
        size_t idx = (size_t)r * C + j;
        float v = fmaxf(Y[idx] * scale + shift, 0.f);
        if (resid) v += resid[idx];
        H[idx] = v;
        if (outw) outw[idx] = w0 * v;
    }
}

// ---------------- CSR build: histogram -> scan -> scatter --------------------
__global__ void k_hist(const int* __restrict__ dst) {
    int t = blockIdx.x * blockDim.x + threadIdx.x;
    int stride = gridDim.x * blockDim.x;
    for (int e = t; e < EE; e += stride) atomicAdd(&g_deg[dst[e]], 1);
}

__global__ void k_scan() {  // one block, 1024 threads
    __shared__ int ss[1024];
    int t = threadIdx.x;
    const int CH = (NN + 1023) / 1024;
    int lo = t * CH;
    int hi = lo + CH; if (hi > NN) hi = NN;
    int loc = 0;
    for (int i = lo; i < hi; i++) loc += g_deg[i];
    ss[t] = loc;
    __syncthreads();
    for (int off = 1; off < 1024; off <<= 1) {
        int v = (t >= off) ? ss[t - off] : 0;
        __syncthreads();
        ss[t] += v;
        __syncthreads();
    }
    int run = ss[t] - loc;  // exclusive prefix
    for (int i = lo; i < hi; i++) {
        g_rowptr[i] = run;
        g_cursor[i] = run;
        run += g_deg[i];
    }
    if (t == 1023) g_rowptr[NN] = ss[1023];
}

__global__ void k_scatter(const int* __restrict__ src, const int* __restrict__ dst) {
    int t = blockIdx.x * blockDim.x + threadIdx.x;
    int stride = gridDim.x * blockDim.x;
    for (int e = t; e < EE; e += stride) {
        int d = dst[e];
        int p = atomicAdd(&g_cursor[d], 1);
        g_colidx[p] = src[e];
    }
}

// ---------------- propagation hop: warp-per-dst gather-reduce ----------------
// nxt[d] = sum over in-edges of cur[src]; OUT[d] += w[hop+1] * nxt[d]
__global__ __launch_bounds__(256)
void k_hop(int hop) {
    const float* __restrict__ cur = (hop & 1) ? g_NXT : g_CUR;
    float* __restrict__ nxt       = (hop & 1) ? g_CUR : g_NXT;
    int warp = (blockIdx.x * blockDim.x + threadIdx.x) >> 5;
    int lane = threadIdx.x & 31;
    if (warp >= NN) return;
    float w = g_w[hop + 1];
    int s = g_rowptr[warp];
    int e = g_rowptr[warp + 1];
    float4 acc0 = make_float4(0.f, 0.f, 0.f, 0.f);
    float4 acc1 = make_float4(0.f, 0.f, 0.f, 0.f);
    int i = s;
    for (; i + 1 < e; i += 2) {
        int s0 = __ldg(&g_colidx[i]);
        int s1 = __ldg(&g_colidx[i + 1]);
        float4 v0 = *(const float4*)(cur + (size_t)s0 * HD + lane * 4);
        float4 v1 = *(const float4*)(cur + (size_t)s1 * HD + lane * 4);
        acc0.x += v0.x; acc0.y += v0.y; acc0.z += v0.z; acc0.w += v0.w;
        acc1.x += v1.x; acc1.y += v1.y; acc1.z += v1.z; acc1.w += v1.w;
    }
    if (i < e) {
        int s0 = __ldg(&g_colidx[i]);
        float4 v0 = *(const float4*)(cur + (size_t)s0 * HD + lane * 4);
        acc0.x += v0.x; acc0.y += v0.y; acc0.z += v0.z; acc0.w += v0.w;
    }
    float4 a = make_float4(acc0.x + acc1.x, acc0.y + acc1.y,
                           acc0.z + acc1.z, acc0.w + acc1.w);
    size_t base = (size_t)warp * HD + lane * 4;
    *(float4*)(nxt + base) = a;
    float4 o = *(float4*)(g_OUT + base);
    o.x += w * a.x; o.y += w * a.y; o.z += w * a.z; o.w += w * a.w;
    *(float4*)(g_OUT + base) = o;
}

// ---------------- host launcher ----------------------------------------------
extern "C" void kernel_launch(void* const* d_in, const int* in_sizes, int n_in,
                              void* d_out, int out_size) {
    const float* x    = (const float*)d_in[0];
    const int*   ei   = (const int*)d_in[1];
    const float* W1   = (const float*)d_in[2];
    const float* b1   = (const float*)d_in[3];
    const float* g1   = (const float*)d_in[4];
    const float* be1  = (const float*)d_in[5];
    const float* W2   = (const float*)d_in[6];
    const float* b2   = (const float*)d_in[7];
    const float* g2   = (const float*)d_in[8];
    const float* be2  = (const float*)d_in[9];
    const float* att  = (const float*)d_in[10];
    const float* W3   = (const float*)d_in[11];
    const float* b3   = (const float*)d_in[12];
    const float* g3   = (const float*)d_in[13];
    const float* be3  = (const float*)d_in[14];
    const float* Wout = (const float*)d_in[15];
    const float* bout = (const float*)d_in[16];
    const int* srcp = ei;
    const int* dstp = ei + EE;
    float* out = (float*)d_out;

    float *Y, *H1, *CUR, *OUT, *H3, *S1, *Q1, *S2, *Q2, *S3, *Q3;
    cudaGetSymbolAddress((void**)&Y,   g_Y);
    cudaGetSymbolAddress((void**)&H1,  g_H1);
    cudaGetSymbolAddress((void**)&CUR, g_CUR);
    cudaGetSymbolAddress((void**)&OUT, g_OUT);
    cudaGetSymbolAddress((void**)&H3,  g_H3);
    cudaGetSymbolAddress((void**)&S1,  g_S1);
    cudaGetSymbolAddress((void**)&Q1,  g_Q1);
    cudaGetSymbolAddress((void**)&S2,  g_S2);
    cudaGetSymbolAddress((void**)&Q2,  g_Q2);
    cudaGetSymbolAddress((void**)&S3,  g_S3);
    cudaGetSymbolAddress((void**)&Q3,  g_Q3);

    const int MB = (NN + 63) / 64;  // 782 row-tiles

    k_init<<<200, 256>>>(att);

    // layer 1: h1 = relu(bn(x @ W1 + b1))
    k_gemm<<<dim3(2, MB), 256>>>(x, W1, b1, Y, NN, HD, IN_DIM);
    k_stats<<<512, HD>>>(Y, S1, Q1, NN, HD);
    k_apply<<<1024, HD>>>(Y, g1, be1, S1, Q1, H1, nullptr, nullptr, NN, HD);

    // layer 2: cur = relu(bn(h1 @ W2 + b2)) + h1 ; OUT = w0 * cur
    k_gemm<<<dim3(2, MB), 256>>>(H1, W2, b2, Y, NN, HD, HD);
    k_stats<<<512, HD>>>(Y, S2, Q2, NN, HD);
    k_apply<<<1024, HD>>>(Y, g2, be2, S2, Q2, CUR, H1, OUT, NN, HD);

    // CSR by destination
    k_hist<<<1024, 256>>>(dstp);
    k_scan<<<1, 1024>>>();
    k_scatter<<<1024, 256>>>(srcp, dstp);

    // K hops, fused weighted accumulation
    for (int h = 0; h < KHOPS; h++)
        k_hop<<<(NN * 32 + 255) / 256, 256>>>(h);

    // output MLP
    k_gemm<<<dim3(1, MB), 256>>>(OUT, W3, b3, Y, NN, HD2, HD);
    k_stats<<<512, HD2>>>(Y, S3, Q3, NN, HD2);
    k_apply<<<1024, HD2>>>(Y, g3, be3, S3, Q3, H3, nullptr, nullptr, NN, HD2);
    k_gemm<<<dim3((OUT_DIM + 63) / 64, MB), 256>>>(H3, Wout, bout, out, NN, OUT_DIM, HD2);
}

// round 3
// speedup vs baseline: 1.2013x; 1.2013x over previous
#include <cuda_runtime.h>
#include <math.h>

#define NN 50000
#define EE 800000
#define IN_DIM 128
#define HD 128
#define HD2 64
#define OUT_DIM 1000
#define KHOPS 10
#define EPSV 1e-5f

// ---------------- scratch (device globals; no allocation allowed) ------------
__device__ float g_Y[(size_t)NN * HD];     // pre-BN scratch (layers 1/2)
__device__ float g_H1[(size_t)NN * HD];    // layer-1 output (residual identity)
__device__ float g_H2[(size_t)NN * HD];    // layer-2 output (propagation seed, 128d)
__device__ float g_P[(size_t)NN * HD2];    // projected 64d hop ping
__device__ float g_PB[(size_t)NN * HD2];   // hop pong
__device__ float g_O64[(size_t)NN * HD2];  // softmax-weighted accumulator (64d)
__device__ float g_H3[(size_t)NN * HD2];
__device__ float g_S1[HD], g_Q1[HD], g_S2[HD], g_Q2[HD], g_S3[HD2], g_Q3[HD2];
__device__ float g_w[KHOPS + 1];
__device__ int   g_deg[NN];
__device__ int   g_rowptr[NN + 1];
__device__ int   g_cursor[NN];
__device__ int   g_colidx[EE];

// ---------------- init: zero stats/degrees, softmax(att) ---------------------
__global__ void k_init(const float* __restrict__ att) {
    int t = blockIdx.x * blockDim.x + threadIdx.x;
    int stride = gridDim.x * blockDim.x;
    for (int i = t; i < NN; i += stride) g_deg[i] = 0;
    if (t < HD)  { g_S1[t] = 0.f; g_Q1[t] = 0.f; g_S2[t] = 0.f; g_Q2[t] = 0.f; }
    if (t < HD2) { g_S3[t] = 0.f; g_Q3[t] = 0.f; }
    if (t == 0) {
        float m = -1e30f;
        for (int i = 0; i <= KHOPS; i++) m = fmaxf(m, att[i]);
        float e[KHOPS + 1]; float s = 0.f;
        for (int i = 0; i <= KHOPS; i++) { e[i] = expf(att[i] - m); s += e[i]; }
        for (int i = 0; i <= KHOPS; i++) g_w[i] = e[i] / s;
    }
}

// ---------------- guarded tiled GEMM: C = A[M,K] @ B[K,Nc] (+bias) -----------
// BM=BN=64, BK=16, 256 threads, 4x4 register tile. Optional fused BN column
// stats (sum / sumsq over valid rows) via shared partials + per-column atomics.
__global__ __launch_bounds__(256)
void k_gemm(const float* __restrict__ A, const float* __restrict__ B,
            const float* __restrict__ bias, float* __restrict__ C,
            float* __restrict__ Sp, float* __restrict__ Qp,
            int M, int Nc, int K) {
    __shared__ float As[64][17];
    __shared__ float Bs[16][68];
    __shared__ float cS[64], cQ[64];
    int tid = threadIdx.x;
    int tx = tid & 15, ty = tid >> 4;
    int rowBase = blockIdx.y * 64;
    int colBase = blockIdx.x * 64;
    float acc[4][4] = {};

    if (Sp && tid < 64) { cS[tid] = 0.f; cQ[tid] = 0.f; }

    for (int k0 = 0; k0 < K; k0 += 16) {
        {   // A tile: 64 rows x 16 k, one float4 per thread
            int r = tid >> 2, c = (tid & 3) * 4;
            int gr = rowBase + r;
            float4 v = make_float4(0.f, 0.f, 0.f, 0.f);
            if (gr < M) v = *(const float4*)(A + (size_t)gr * K + k0 + c);
            As[r][c] = v.x; As[r][c + 1] = v.y; As[r][c + 2] = v.z; As[r][c + 3] = v.w;
        }
        {   // B tile: 16 k x 64 cols, one float4 per thread
            int r = tid >> 4, c = (tid & 15) * 4;
            int gc = colBase + c;
            float4 v = make_float4(0.f, 0.f, 0.f, 0.f);
            if (gc < Nc) v = *(const float4*)(B + (size_t)(k0 + r) * Nc + gc);
            Bs[r][c] = v.x; Bs[r][c + 1] = v.y; Bs[r][c + 2] = v.z; Bs[r][c + 3] = v.w;
        }
        __syncthreads();
        #pragma unroll
        for (int kk = 0; kk < 16; kk++) {
            float a[4], b[4];
            #pragma unroll
            for (int i = 0; i < 4; i++) a[i] = As[ty * 4 + i][kk];
            #pragma unroll
            for (int j = 0; j < 4; j++) b[j] = Bs[kk][tx * 4 + j];
            #pragma unroll
            for (int i = 0; i < 4; i++)
                #pragma unroll
                for (int j = 0; j < 4; j++)
                    acc[i][j] = fmaf(a[i], b[j], acc[i][j]);
        }
        __syncthreads();
    }
    #pragma unroll
    for (int i = 0; i < 4; i++) {
        int r = rowBase + ty * 4 + i;
        if (r >= M) continue;
        #pragma unroll
        for (int j = 0; j < 4; j++) {
            int c = colBase + tx * 4 + j;
            if (c < Nc) {
                float v = acc[i][j];
                if (bias) v += bias[c];
                C[(size_t)r * Nc + c] = v;
            }
        }
    }
    if (Sp) {
        float s[4] = {0.f, 0.f, 0.f, 0.f};
        float q[4] = {0.f, 0.f, 0.f, 0.f};
        #pragma unroll
        for (int i = 0; i < 4; i++) {
            int r = rowBase + ty * 4 + i;
            if (r >= M) continue;
            #pragma unroll
            for (int j = 0; j < 4; j++) {
                float v = acc[i][j];
                s[j] += v; q[j] += v * v;
            }
        }
        #pragma unroll
        for (int j = 0; j < 4; j++) {
            atomicAdd(&cS[tx * 4 + j], s[j]);
            atomicAdd(&cQ[tx * 4 + j], q[j]);
        }
        __syncthreads();
        if (tid < 64) {
            int c = colBase + tid;
            if (c < Nc) {
                atomicAdd(Sp + c, cS[tid]);
                atomicAdd(Qp + c, cQ[tid]);
            }
        }
    }
}

// ---------------- BN apply + ReLU (+residual), vectorized float4 -------------
__global__ __launch_bounds__(256)
void k_apply(const float* __restrict__ Y, const float* __restrict__ g,
             const float* __restrict__ be, const float* __restrict__ S,
             const float* __restrict__ Q, float* __restrict__ H,
             const float* __restrict__ resid, int M, int C) {
    __shared__ float4 sc4[32], sh4[32];
    int tid = threadIdx.x;
    int c4 = C >> 2;
    if (tid < c4) {
        float4 s4, h4;
        float* sp = (float*)&s4;
        float* hp = (float*)&h4;
        #pragma unroll
        for (int k = 0; k < 4; k++) {
            int col = tid * 4 + k;
            float mean = S[col] / (float)M;
            float var = Q[col] / (float)M - mean * mean;
            float rstd = rsqrtf(var + EPSV);
            float scale = g[col] * rstd;
            sp[k] = scale;
            hp[k] = be[col] - mean * scale;
        }
        sc4[tid] = s4; sh4[tid] = h4;
    }
    __syncthreads();
    int total = M * c4;
    int stride = gridDim.x * blockDim.x;
    int mask = c4 - 1;  // c4 is 16 or 32 (power of two)
    for (int idx = blockIdx.x * blockDim.x + tid; idx < total; idx += stride) {
        int j4 = idx & mask;
        float4 y = ((const float4*)Y)[idx];
        float4 sc = sc4[j4], sh = sh4[j4];
        float4 r;
        r.x = fmaxf(fmaf(y.x, sc.x, sh.x), 0.f);
        r.y = fmaxf(fmaf(y.y, sc.y, sh.y), 0.f);
        r.z = fmaxf(fmaf(y.z, sc.z, sh.z), 0.f);
        r.w = fmaxf(fmaf(y.w, sc.w, sh.w), 0.f);
        if (resid) {
            float4 rr = ((const float4*)resid)[idx];
            r.x += rr.x; r.y += rr.y; r.z += rr.z; r.w += rr.w;
        }
        ((float4*)H)[idx] = r;
    }
}

// ---------------- column stats for OUT64 (final BN) --------------------------
__global__ __launch_bounds__(256)
void k_stats64(const float* __restrict__ Y, float* __restrict__ S,
               float* __restrict__ Q, int M) {
    int col = threadIdx.x & 63;
    int rg = threadIdx.x >> 6;  // 0..3
    float s = 0.f, q = 0.f;
    for (int r = blockIdx.x * 4 + rg; r < M; r += gridDim.x * 4) {
        float v = Y[(size_t)r * HD2 + col];
        s += v; q += v * v;
    }
    atomicAdd(S + col, s);
    atomicAdd(Q + col, q);
}

// ---------------- CSR build: histogram -> scan -> scatter --------------------
__global__ void k_hist(const int* __restrict__ dst) {
    int t = blockIdx.x * blockDim.x + threadIdx.x;
    int stride = gridDim.x * blockDim.x;
    for (int e = t; e < EE; e += stride) atomicAdd(&g_deg[dst[e]], 1);
}

__global__ void k_scan() {  // one block, 1024 threads
    __shared__ int ss[1024];
    int t = threadIdx.x;
    const int CH = (NN + 1023) / 1024;
    int lo = t * CH;
    int hi = lo + CH; if (hi > NN) hi = NN;
    int loc = 0;
    for (int i = lo; i < hi; i++) loc += g_deg[i];
    ss[t] = loc;
    __syncthreads();
    for (int off = 1; off < 1024; off <<= 1) {
        int v = (t >= off) ? ss[t - off] : 0;
        __syncthreads();
        ss[t] += v;
        __syncthreads();
    }
    int run = ss[t] - loc;  // exclusive prefix
    for (int i = lo; i < hi; i++) {
        g_rowptr[i] = run;
        g_cursor[i] = run;
        run += g_deg[i];
    }
    if (t == 1023) g_rowptr[NN] = ss[1023];
}

__global__ void k_scatter(const int* __restrict__ src, const int* __restrict__ dst) {
    int t = blockIdx.x * blockDim.x + threadIdx.x;
    int stride = gridDim.x * blockDim.x;
    for (int e = t; e < EE; e += stride) {
        int d = dst[e];
        int p = atomicAdd(&g_cursor[d], 1);
        g_colidx[p] = src[e];
    }
}

// ---------------- 64d propagation hop: half-warp-per-dst gather-reduce -------
// nxt[d] = sum_{in-edges} cur[src];  O64[d] = (hop==0 ? w0*cur[d] : O64[d]) + w[hop+1]*nxt[d]
__global__ __launch_bounds__(256)
void k_hop64(int hop) {
    const float* __restrict__ cur = (hop & 1) ? g_PB : g_P;
    float* __restrict__ nxt       = (hop & 1) ? g_P : g_PB;
    int gid = blockIdx.x * blockDim.x + threadIdx.x;
    int d = gid >> 4;            // half-warp per destination node
    int lane = threadIdx.x & 15;
    if (d >= NN) return;
    float w = g_w[hop + 1];
    int s = g_rowptr[d];
    int e = g_rowptr[d + 1];
    float4 acc0 = make_float4(0.f, 0.f, 0.f, 0.f);
    float4 acc1 = make_float4(0.f, 0.f, 0.f, 0.f);
    int i = s;
    for (; i + 1 < e; i += 2) {
        int s0 = __ldg(&g_colidx[i]);
        int s1 = __ldg(&g_colidx[i + 1]);
        float4 v0 = *(const float4*)(cur + (size_t)s0 * HD2 + lane * 4);
        float4 v1 = *(const float4*)(cur + (size_t)s1 * HD2 + lane * 4);
        acc0.x += v0.x; acc0.y += v0.y; acc0.z += v0.z; acc0.w += v0.w;
        acc1.x += v1.x; acc1.y += v1.y; acc1.z += v1.z; acc1.w += v1.w;
    }
    if (i < e) {
        int s0 = __ldg(&g_colidx[i]);
        float4 v0 = *(const float4*)(cur + (size_t)s0 * HD2 + lane * 4);
        acc0.x += v0.x; acc0.y += v0.y; acc0.z += v0.z; acc0.w += v0.w;
    }
    float4 a = make_float4(acc0.x + acc1.x, acc0.y + acc1.y,
                           acc0.z + acc1.z, acc0.w + acc1.w);
    size_t base = (size_t)d * HD2 + lane * 4;
    *(float4*)(nxt + base) = a;
    float4 o;
    if (hop == 0) {
        float w0 = g_w[0];
        float4 c = *(const float4*)(cur + base);
        o = make_float4(w0 * c.x, w0 * c.y, w0 * c.z, w0 * c.w);
    } else {
        o = *(float4*)(g_O64 + base);
    }
    o.x += w * a.x; o.y += w * a.y; o.z += w * a.z; o.w += w * a.w;
    *(float4*)(g_O64 + base) = o;
}

// ---------------- host launcher ----------------------------------------------
extern "C" void kernel_launch(void* const* d_in, const int* in_sizes, int n_in,
                              void* d_out, int out_size) {
    const float* x    = (const float*)d_in[0];
    const int*   ei   = (const int*)d_in[1];
    const float* W1   = (const float*)d_in[2];
    const float* g1   = (const float*)d_in[4];
    const float* be1  = (const float*)d_in[5];
    const float* W2   = (const float*)d_in[6];
    const float* g2   = (const float*)d_in[8];
    const float* be2  = (const float*)d_in[9];
    const float* att  = (const float*)d_in[10];
    const float* W3   = (const float*)d_in[11];
    const float* g3   = (const float*)d_in[13];
    const float* be3  = (const float*)d_in[14];
    const float* Wout = (const float*)d_in[15];
    const float* bout = (const float*)d_in[16];
    // b1/b2/b3 dropped: BN is invariant to per-column constant shifts.
    const int* srcp = ei;
    const int* dstp = ei + EE;
    float* out = (float*)d_out;

    float *Y, *H1, *H2, *P, *O64, *H3, *S1, *Q1, *S2, *Q2, *S3, *Q3;
    cudaGetSymbolAddress((void**)&Y,   g_Y);
    cudaGetSymbolAddress((void**)&H1,  g_H1);
    cudaGetSymbolAddress((void**)&H2,  g_H2);
    cudaGetSymbolAddress((void**)&P,   g_P);
    cudaGetSymbolAddress((void**)&O64, g_O64);
    cudaGetSymbolAddress((void**)&H3,  g_H3);
    cudaGetSymbolAddress((void**)&S1,  g_S1);
    cudaGetSymbolAddress((void**)&Q1,  g_Q1);
    cudaGetSymbolAddress((void**)&S2,  g_S2);
    cudaGetSymbolAddress((void**)&Q2,  g_Q2);
    cudaGetSymbolAddress((void**)&S3,  g_S3);
    cudaGetSymbolAddress((void**)&Q3,  g_Q3);

    const int MB = (NN + 63) / 64;  // 782 row-tiles

    k_init<<<200, 256>>>(att);

    // CSR by destination (independent of MLP; do it early)
    k_hist<<<1024, 256>>>(dstp);
    k_scan<<<1, 1024>>>();
    k_scatter<<<1024, 256>>>(srcp, dstp);

    // layer 1: h1 = relu(bn(x @ W1))           [stats fused in GEMM]
    k_gemm<<<dim3(2, MB), 256>>>(x, W1, nullptr, Y, S1, Q1, NN, HD, IN_DIM);
    k_apply<<<2048, 256>>>(Y, g1, be1, S1, Q1, H1, nullptr, NN, HD);

    // layer 2: h2 = relu(bn(h1 @ W2)) + h1     [stats fused in GEMM]
    k_gemm<<<dim3(2, MB), 256>>>(H1, W2, nullptr, Y, S2, Q2, NN, HD, HD);
    k_apply<<<2048, 256>>>(Y, g2, be2, S2, Q2, H2, H1, NN, HD);

    // project to 64d BEFORE propagation: P = h2 @ W3  (A^i and W3 commute)
    k_gemm<<<dim3(1, MB), 256>>>(H2, W3, nullptr, P, nullptr, nullptr, NN, HD2, HD);

    // K hops in 64d; weighted accumulation fused (hop 0 seeds O64 = w0*P)
    for (int h = 0; h < KHOPS; h++)
        k_hop64<<<(NN * 16 + 255) / 256, 256>>>(h);

    // output MLP: h3 = relu(bn(O64)); out = h3 @ Wout + bout
    k_stats64<<<1024, 256>>>(O64, S3, Q3, NN);
    k_apply<<<2048, 256>>>(O64, g3, be3, S3, Q3, H3, nullptr, NN, HD2);
    k_gemm<<<dim3((OUT_DIM + 63) / 64, MB), 256>>>(H3, Wout, bout, out,
                                                   nullptr, nullptr, NN, OUT_DIM, HD2);
}

// round 4
// speedup vs baseline: 1.2875x; 1.0718x over previous
#include <cuda_runtime.h>
#include <math.h>

#define NN 50000
#define EE 800000
#define IN_DIM 128
#define HD 128
#define HD2 64
#define OUT_DIM 1000
#define KHOPS 10
#define EPSV 1e-5f

// ---------------- scratch (device globals; no allocation allowed) ------------
__device__ float g_Y[(size_t)NN * HD];     // pre-BN scratch (layers 1/2)
__device__ float g_H1[(size_t)NN * HD];    // layer-1 output (residual identity)
__device__ float g_H2[(size_t)NN * HD];    // layer-2 output
__device__ float g_P[(size_t)NN * HD2];    // projected 64d hop ping
__device__ float g_PB[(size_t)NN * HD2];   // hop pong
__device__ float g_O64[(size_t)NN * HD2];  // softmax-weighted accumulator (64d)
__device__ float g_H3[(size_t)NN * HD2];
__device__ float g_S1[HD], g_Q1[HD], g_S2[HD], g_Q2[HD], g_S3[HD2], g_Q3[HD2];
__device__ float g_w[KHOPS + 1];
__device__ int   g_deg[NN];
__device__ int   g_rowptr[NN + 1];
__device__ int   g_cursor[NN];
__device__ int   g_colidx[EE];

// ---------------- init: zero stats/degrees, softmax(att) ---------------------
__global__ void k_init(const float* __restrict__ att) {
    int t = blockIdx.x * blockDim.x + threadIdx.x;
    int stride = gridDim.x * blockDim.x;
    for (int i = t; i < NN; i += stride) g_deg[i] = 0;
    if (t < HD)  { g_S1[t] = 0.f; g_Q1[t] = 0.f; g_S2[t] = 0.f; g_Q2[t] = 0.f; }
    if (t < HD2) { g_S3[t] = 0.f; g_Q3[t] = 0.f; }
    if (t == 0) {
        float m = -1e30f;
        for (int i = 0; i <= KHOPS; i++) m = fmaxf(m, att[i]);
        float e[KHOPS + 1]; float s = 0.f;
        for (int i = 0; i <= KHOPS; i++) { e[i] = expf(att[i] - m); s += e[i]; }
        for (int i = 0; i <= KHOPS; i++) g_w[i] = e[i] / s;
    }
}

// ---------------- tiled GEMM: C = A[M,K] @ B[K,Nc] (+bias) -------------------
// BM=128, BN=64, BK=16, 256 threads, 8x4 register tile per thread.
// Optional fused BN column stats via shared partials + per-column atomics.
__global__ __launch_bounds__(256)
void k_gemm(const float* __restrict__ A, const float* __restrict__ B,
            const float* __restrict__ bias, float* __restrict__ C,
            float* __restrict__ Sp, float* __restrict__ Qp,
            int M, int Nc, int K) {
    __shared__ float As[128][17];
    __shared__ float Bs[16][68];   // rows 272B = 17*16B -> 16B-aligned
    __shared__ float cS[64], cQ[64];
    int tid = threadIdx.x;
    int tx = tid & 15;             // 16 cols of 4
    int ty = tid >> 4;             // 16 rows of 8
    int rowBase = blockIdx.y * 128;
    int colBase = blockIdx.x * 64;
    float acc[8][4] = {};

    if (Sp && tid < 64) { cS[tid] = 0.f; cQ[tid] = 0.f; }

    for (int k0 = 0; k0 < K; k0 += 16) {
        // A tile: 128 rows x 16 k = 512 float4, 2 per thread
        #pragma unroll
        for (int l = 0; l < 2; l++) {
            int f = tid + l * 256;
            int r = f >> 2, c = (f & 3) * 4;
            int gr = rowBase + r;
            float4 v = make_float4(0.f, 0.f, 0.f, 0.f);
            if (gr < M) v = *(const float4*)(A + (size_t)gr * K + k0 + c);
            As[r][c] = v.x; As[r][c + 1] = v.y; As[r][c + 2] = v.z; As[r][c + 3] = v.w;
        }
        {   // B tile: 16 k x 64 cols = 256 float4, 1 per thread
            int r = tid >> 4, c = (tid & 15) * 4;
            int gc = colBase + c;
            float4 v = make_float4(0.f, 0.f, 0.f, 0.f);
            if (gc < Nc) v = *(const float4*)(B + (size_t)(k0 + r) * Nc + gc);
            Bs[r][c] = v.x; Bs[r][c + 1] = v.y; Bs[r][c + 2] = v.z; Bs[r][c + 3] = v.w;
        }
        __syncthreads();
        #pragma unroll
        for (int kk = 0; kk < 16; kk++) {
            float4 bv = *(const float4*)&Bs[kk][tx * 4];
            float a[8];
            #pragma unroll
            for (int i = 0; i < 8; i++) a[i] = As[ty * 8 + i][kk];
            #pragma unroll
            for (int i = 0; i < 8; i++) {
                acc[i][0] = fmaf(a[i], bv.x, acc[i][0]);
                acc[i][1] = fmaf(a[i], bv.y, acc[i][1]);
                acc[i][2] = fmaf(a[i], bv.z, acc[i][2]);
                acc[i][3] = fmaf(a[i], bv.w, acc[i][3]);
            }
        }
        __syncthreads();
    }
    #pragma unroll
    for (int i = 0; i < 8; i++) {
        int r = rowBase + ty * 8 + i;
        if (r >= M) continue;
        #pragma unroll
        for (int j = 0; j < 4; j++) {
            int c = colBase + tx * 4 + j;
            if (c < Nc) {
                float v = acc[i][j];
                if (bias) v += bias[c];
                C[(size_t)r * Nc + c] = v;
            }
        }
    }
    if (Sp) {
        float s[4] = {0.f, 0.f, 0.f, 0.f};
        float q[4] = {0.f, 0.f, 0.f, 0.f};
        #pragma unroll
        for (int i = 0; i < 8; i++) {
            int r = rowBase + ty * 8 + i;
            if (r >= M) continue;
            #pragma unroll
            for (int j = 0; j < 4; j++) {
                float v = acc[i][j];
                s[j] += v; q[j] += v * v;
            }
        }
        #pragma unroll
        for (int j = 0; j < 4; j++) {
            atomicAdd(&cS[tx * 4 + j], s[j]);
            atomicAdd(&cQ[tx * 4 + j], q[j]);
        }
        __syncthreads();
        if (tid < 64) {
            int c = colBase + tid;
            if (c < Nc) {
                atomicAdd(Sp + c, cS[tid]);
                atomicAdd(Qp + c, cQ[tid]);
            }
        }
    }
}

// ---------------- BN apply + ReLU (+residual), vectorized float4 -------------
__global__ __launch_bounds__(256)
void k_apply(const float* __restrict__ Y, const float* __restrict__ g,
             const float* __restrict__ be, const float* __restrict__ S,
             const float* __restrict__ Q, float* __restrict__ H,
             const float* __restrict__ resid, int M, int C) {
    __shared__ float4 sc4[32], sh4[32];
    int tid = threadIdx.x;
    int c4 = C >> 2;
    if (tid < c4) {
        float4 s4, h4;
        float* sp = (float*)&s4;
        float* hp = (float*)&h4;
        #pragma unroll
        for (int k = 0; k < 4; k++) {
            int col = tid * 4 + k;
            float mean = S[col] / (float)M;
            float var = Q[col] / (float)M - mean * mean;
            float rstd = rsqrtf(var + EPSV);
            float scale = g[col] * rstd;
            sp[k] = scale;
            hp[k] = be[col] - mean * scale;
        }
        sc4[tid] = s4; sh4[tid] = h4;
    }
    __syncthreads();
    int total = M * c4;
    int stride = gridDim.x * blockDim.x;
    int mask = c4 - 1;  // c4 is 16 or 32 (power of two)
    for (int idx = blockIdx.x * blockDim.x + tid; idx < total; idx += stride) {
        int j4 = idx & mask;
        float4 y = ((const float4*)Y)[idx];
        float4 sc = sc4[j4], sh = sh4[j4];
        float4 r;
        r.x = fmaxf(fmaf(y.x, sc.x, sh.x), 0.f);
        r.y = fmaxf(fmaf(y.y, sc.y, sh.y), 0.f);
        r.z = fmaxf(fmaf(y.z, sc.z, sh.z), 0.f);
        r.w = fmaxf(fmaf(y.w, sc.w, sh.w), 0.f);
        if (resid) {
            float4 rr = ((const float4*)resid)[idx];
            r.x += rr.x; r.y += rr.y; r.z += rr.z; r.w += rr.w;
        }
        ((float4*)H)[idx] = r;
    }
}

// ---------------- column stats for OUT64 (final BN) --------------------------
__global__ __launch_bounds__(256)
void k_stats64(const float* __restrict__ Y, float* __restrict__ S,
               float* __restrict__ Q, int M) {
    int col = threadIdx.x & 63;
    int rg = threadIdx.x >> 6;  // 0..3
    float s = 0.f, q = 0.f;
    for (int r = blockIdx.x * 4 + rg; r < M; r += gridDim.x * 4) {
        float v = Y[(size_t)r * HD2 + col];
        s += v; q += v * v;
    }
    atomicAdd(S + col, s);
    atomicAdd(Q + col, q);
}

// ---------------- CSR build: histogram -> scan -> scatter --------------------
__global__ void k_hist(const int* __restrict__ dst) {
    int t = blockIdx.x * blockDim.x + threadIdx.x;
    int stride = gridDim.x * blockDim.x;
    for (int e = t; e < EE; e += stride) atomicAdd(&g_deg[dst[e]], 1);
}

__global__ void k_scan() {  // one block, 1024 threads
    __shared__ int ss[1024];
    int t = threadIdx.x;
    const int CH = (NN + 1023) / 1024;
    int lo = t * CH;
    int hi = lo + CH; if (hi > NN) hi = NN;
    int loc = 0;
    for (int i = lo; i < hi; i++) loc += g_deg[i];
    ss[t] = loc;
    __syncthreads();
    for (int off = 1; off < 1024; off <<= 1) {
        int v = (t >= off) ? ss[t - off] : 0;
        __syncthreads();
        ss[t] += v;
        __syncthreads();
    }
    int run = ss[t] - loc;  // exclusive prefix
    for (int i = lo; i < hi; i++) {
        g_rowptr[i] = run;
        g_cursor[i] = run;
        run += g_deg[i];
    }
    if (t == 1023) g_rowptr[NN] = ss[1023];
}

__global__ void k_scatter(const int* __restrict__ src, const int* __restrict__ dst) {
    int t = blockIdx.x * blockDim.x + threadIdx.x;
    int stride = gridDim.x * blockDim.x;
    for (int e = t; e < EE; e += stride) {
        int d = dst[e];
        int p = atomicAdd(&g_cursor[d], 1);
        g_colidx[p] = src[e];
    }
}

// ---------------- 64d propagation hop: half-warp-per-dst gather-reduce -------
// nxt[d] = sum_{in-edges} cur[src];  O64[d] = (hop==0 ? w0*cur[d] : O64[d]) + w[hop+1]*nxt[d]
__global__ __launch_bounds__(256)
void k_hop64(int hop) {
    const float* __restrict__ cur = (hop & 1) ? g_PB : g_P;
    float* __restrict__ nxt       = (hop & 1) ? g_P : g_PB;
    int gid = blockIdx.x * blockDim.x + threadIdx.x;
    int d = gid >> 4;            // half-warp per destination node
    int lane = threadIdx.x & 15;
    if (d >= NN) return;
    float w = g_w[hop + 1];
    int s = g_rowptr[d];
    int e = g_rowptr[d + 1];
    float4 acc0 = make_float4(0.f, 0.f, 0.f, 0.f);
    float4 acc1 = make_float4(0.f, 0.f, 0.f, 0.f);
    float4 acc2 = make_float4(0.f, 0.f, 0.f, 0.f);
    float4 acc3 = make_float4(0.f, 0.f, 0.f, 0.f);
    int i = s;
    for (; i + 3 < e; i += 4) {
        int s0 = __ldg(&g_colidx[i]);
        int s1 = __ldg(&g_colidx[i + 1]);
        int s2 = __ldg(&g_colidx[i + 2]);
        int s3 = __ldg(&g_colidx[i + 3]);
        float4 v0 = *(const float4*)(cur + (size_t)s0 * HD2 + lane * 4);
        float4 v1 = *(const float4*)(cur + (size_t)s1 * HD2 + lane * 4);
        float4 v2 = *(const float4*)(cur + (size_t)s2 * HD2 + lane * 4);
        float4 v3 = *(const float4*)(cur + (size_t)s3 * HD2 + lane * 4);
        acc0.x += v0.x; acc0.y += v0.y; acc0.z += v0.z; acc0.w += v0.w;
        acc1.x += v1.x; acc1.y += v1.y; acc1.z += v1.z; acc1.w += v1.w;
        acc2.x += v2.x; acc2.y += v2.y; acc2.z += v2.z; acc2.w += v2.w;
        acc3.x += v3.x; acc3.y += v3.y; acc3.z += v3.z; acc3.w += v3.w;
    }
    for (; i < e; i++) {
        int s0 = __ldg(&g_colidx[i]);
        float4 v0 = *(const float4*)(cur + (size_t)s0 * HD2 + lane * 4);
        acc0.x += v0.x; acc0.y += v0.y; acc0.z += v0.z; acc0.w += v0.w;
    }
    float4 a = make_float4((acc0.x + acc1.x) + (acc2.x + acc3.x),
                           (acc0.y + acc1.y) + (acc2.y + acc3.y),
                           (acc0.z + acc1.z) + (acc2.z + acc3.z),
                           (acc0.w + acc1.w) + (acc2.w + acc3.w));
    size_t base = (size_t)d * HD2 + lane * 4;
    *(float4*)(nxt + base) = a;
    float4 o;
    if (hop == 0) {
        float w0 = g_w[0];
        float4 c = *(const float4*)(cur + base);
        o = make_float4(w0 * c.x, w0 * c.y, w0 * c.z, w0 * c.w);
    } else {
        o = *(float4*)(g_O64 + base);
    }
    o.x += w * a.x; o.y += w * a.y; o.z += w * a.z; o.w += w * a.w;
    *(float4*)(g_O64 + base) = o;
}

// ---------------- host launcher ----------------------------------------------
extern "C" void kernel_launch(void* const* d_in, const int* in_sizes, int n_in,
                              void* d_out, int out_size) {
    const float* x    = (const float*)d_in[0];
    const int*   ei   = (const int*)d_in[1];
    const float* W1   = (const float*)d_in[2];
    const float* g1   = (const float*)d_in[4];
    const float* be1  = (const float*)d_in[5];
    const float* W2   = (const float*)d_in[6];
    const float* g2   = (const float*)d_in[8];
    const float* be2  = (const float*)d_in[9];
    const float* att  = (const float*)d_in[10];
    const float* W3   = (const float*)d_in[11];
    const float* g3   = (const float*)d_in[13];
    const float* be3  = (const float*)d_in[14];
    const float* Wout = (const float*)d_in[15];
    const float* bout = (const float*)d_in[16];
    // b1/b2/b3 dropped: BN is invariant to per-column constant shifts.
    const int* srcp = ei;
    const int* dstp = ei + EE;
    float* out = (float*)d_out;

    float *Y, *H1, *H2, *P, *O64, *H3, *S1, *Q1, *S2, *Q2, *S3, *Q3;
    cudaGetSymbolAddress((void**)&Y,   g_Y);
    cudaGetSymbolAddress((void**)&H1,  g_H1);
    cudaGetSymbolAddress((void**)&H2,  g_H2);
    cudaGetSymbolAddress((void**)&P,   g_P);
    cudaGetSymbolAddress((void**)&O64, g_O64);
    cudaGetSymbolAddress((void**)&H3,  g_H3);
    cudaGetSymbolAddress((void**)&S1,  g_S1);
    cudaGetSymbolAddress((void**)&Q1,  g_Q1);
    cudaGetSymbolAddress((void**)&S2,  g_S2);
    cudaGetSymbolAddress((void**)&Q2,  g_Q2);
    cudaGetSymbolAddress((void**)&S3,  g_S3);
    cudaGetSymbolAddress((void**)&Q3,  g_Q3);

    const int MB = (NN + 127) / 128;  // 391 row-tiles

    k_init<<<200, 256>>>(att);

    // CSR by destination (independent of MLP; do it early)
    k_hist<<<1024, 256>>>(dstp);
    k_scan<<<1, 1024>>>();
    k_scatter<<<1024, 256>>>(srcp, dstp);

    // layer 1: h1 = relu(bn(x @ W1))           [stats fused in GEMM]
    k_gemm<<<dim3(2, MB), 256>>>(x, W1, nullptr, Y, S1, Q1, NN, HD, IN_DIM);
    k_apply<<<2048, 256>>>(Y, g1, be1, S1, Q1, H1, nullptr, NN, HD);

    // layer 2: h2 = relu(bn(h1 @ W2)) + h1     [stats fused in GEMM]
    k_gemm<<<dim3(2, MB), 256>>>(H1, W2, nullptr, Y, S2, Q2, NN, HD, HD);
    k_apply<<<2048, 256>>>(Y, g2, be2, S2, Q2, H2, H1, NN, HD);

    // project to 64d BEFORE propagation: P = h2 @ W3  (A^i and W3 commute)
    k_gemm<<<dim3(1, MB), 256>>>(H2, W3, nullptr, P, nullptr, nullptr, NN, HD2, HD);

    // K hops in 64d; weighted accumulation fused (hop 0 seeds O64 = w0*P)
    for (int h = 0; h < KHOPS; h++)
        k_hop64<<<(NN * 16 + 255) / 256, 256>>>(h);

    // output MLP: h3 = relu(bn(O64)); out = h3 @ Wout + bout
    k_stats64<<<1024, 256>>>(O64, S3, Q3, NN);
    k_apply<<<2048, 256>>>(O64, g3, be3, S3, Q3, H3, nullptr, NN, HD2);
    k_gemm<<<dim3((OUT_DIM + 63) / 64, MB), 256>>>(H3, Wout, bout, out,
                                                   nullptr, nullptr, NN, OUT_DIM, HD2);
}